// round 12
// baseline (speedup 1.0000x reference)
#include <cuda_runtime.h>
#include <cuda_fp16.h>
#include <math.h>
#include <stdint.h>

// ---------------- problem constants ----------------
#define VOCAB   8192
#define DIM     512
#define M_ROWS  32768          // 8*4096
#define MOM     0.995f
// output packing (flat f32, tuple order): x_q | loss | perplexity | new_dict | new_counts
#define OFF_LOSS 16777216ull
#define OFF_PERP 16777217ull
#define OFF_DICT 16777218ull
#define OFF_CNT  20971522ull   // OFF_DICT + VOCAB*DIM

// ---------------- GEMM tiling (pass 1, fp16-hi approx) ----------------
#define TM      128
#define TN      256
#define KC      32             // floats per K chunk
#define NCHUNK  (DIM / KC)     // 16
#define MARGIN  0.02f
#define CAP     16777216       // candidate capacity
// stage: A 8KB + B 16KB ; 4 stages
#define STAGE_BYTES 24576
#define SM_H     98304         // 4*24576
#define SM_BEST  99328
#define SM_TOTAL 100352

// ---------------- device scratch (static; no allocations) ----------------
__device__ float               g_e[VOCAB * DIM];
__device__ float               g_h[VOCAB];          // 0.5*||e||^2
__device__ unsigned long long  g_best[M_ROWS];      // approx (pass-1) packed keys
__device__ unsigned long long  g_best2[M_ROWS];     // exact (pass-2) packed keys
__device__ float               g_cnt[VOCAB];
__device__ double              g_loss;
__device__ unsigned int        g_ncand;
__device__ uint32_t            g_cand[CAP];         // row*8192+col
// fragment-packed fp16 hi-limb operands
__device__ uint32_t            g_xh[M_ROWS * DIM / 2];   // 32MB
__device__ uint32_t            g_eh[VOCAB  * DIM / 2];   // 8MB

// ---------------- helpers ----------------
__device__ __forceinline__ uint32_t smem_u32(const void* p) {
    uint32_t a;
    asm("{ .reg .u64 t; cvta.to.shared.u64 t, %1; cvt.u32.u64 %0, t; }" : "=r"(a) : "l"(p));
    return a;
}
__device__ __forceinline__ void cp16(uint32_t dst, const void* src) {
    asm volatile("cp.async.ca.shared.global [%0], [%1], 16;" :: "r"(dst), "l"(src));
}
#define CP_COMMIT() asm volatile("cp.async.commit_group;")
#define CP_WAIT(n)  asm volatile("cp.async.wait_group %0;" :: "n"(n))

#define MMA16(d, a0, a1, a2, a3, b0, b1)                                      \
    asm volatile(                                                             \
        "mma.sync.aligned.m16n8k16.row.col.f32.f16.f16.f32 "                  \
        "{%0,%1,%2,%3}, {%4,%5,%6,%7}, {%8,%9}, {%0,%1,%2,%3};"               \
        : "+f"(d[0]), "+f"(d[1]), "+f"(d[2]), "+f"(d[3])                      \
        : "r"(a0), "r"(a1), "r"(a2), "r"(a3), "r"(b0), "r"(b1))

__device__ __forceinline__ unsigned int fkey(float s) {
    unsigned int ub = __float_as_uint(s);
    return (ub & 0x80000000u) ? ~ub : (ub | 0x80000000u);
}
__device__ __forceinline__ float keyscore(unsigned long long k) {
    unsigned int ub = (unsigned int)(k >> 32);
    unsigned int orig = (ub & 0x80000000u) ? (ub & 0x7fffffffu) : ~ub;
    return __uint_as_float(orig);   // k==0 -> -NaN; callers use fmaxf
}
__device__ __forceinline__ uint32_t pack_h2(float v0, float v1) {
    __half2 p = __halves2half2(__float2half_rn(v0), __float2half_rn(v1));
    return *(uint32_t*)&p;
}

// ---------------- kernel A: codewords + half squared norms ----------------
__global__ void compute_codewords(const float* __restrict__ dict,
                                  const float* __restrict__ counts) {
    int k = blockIdx.x;
    int t = threadIdx.x;
    float inv = 1.0f / counts[k];
    const float4* src = (const float4*)(dict + (size_t)k * DIM);
    float4*       dst = (float4*)(g_e + (size_t)k * DIM);
    float4 v = src[t];
    v.x *= inv; v.y *= inv; v.z *= inv; v.w *= inv;
    dst[t] = v;
    float s = v.x * v.x + v.y * v.y + v.z * v.z + v.w * v.w;
    #pragma unroll
    for (int o = 16; o; o >>= 1) s += __shfl_xor_sync(0xffffffffu, s, o);
    __shared__ float ws[4];
    if ((t & 31) == 0) ws[t >> 5] = s;
    __syncthreads();
    if (t == 0) g_h[k] = 0.5f * (ws[0] + ws[1] + ws[2] + ws[3]);
}

// ---------------- pack X / E into fragment-ordered fp16 hi limbs ----------------
// A u32 index: [mt(256)][c(16)][msub(8)][ks(2)][lane(32)][reg(4)]
__global__ void split_x(const float* __restrict__ X) {
    int o = blockIdx.x * 256 + threadIdx.x;       // 8388608 total
    int reg  =  o        & 3;
    int lane = (o >> 2)  & 31;
    int ks   = (o >> 7)  & 1;
    int msub = (o >> 8)  & 7;
    int c    = (o >> 11) & 15;
    int mt   =  o >> 15;
    int m = mt * 128 + msub * 16 + (lane >> 2) + (reg & 1) * 8;
    int k = c * 32 + ks * 16 + (lane & 3) * 2 + (reg >> 1) * 8;
    const float* xp = X + (size_t)m * DIM + k;
    g_xh[o] = pack_h2(xp[0], xp[1]);
}

// B u32 index: [nt(32)][c(16)][nsub(32)][ks(2)][lane(32)][reg(2)]
__global__ void split_e() {
    int o = blockIdx.x * 256 + threadIdx.x;       // 2097152 total
    int reg  =  o        & 1;
    int lane = (o >> 1)  & 31;
    int ks   = (o >> 6)  & 1;
    int nsub = (o >> 7)  & 31;
    int c    = (o >> 12) & 15;
    int nt   =  o >> 16;
    int n = nt * 256 + nsub * 8 + (lane >> 2);
    int k = c * 32 + ks * 16 + (lane & 3) * 2 + reg * 8;
    const float* ep = g_e + (size_t)n * DIM + k;
    g_eh[o] = pack_h2(ep[0], ep[1]);
}

// ---------------- kernel B: init scratch + new_dict = 0.995*dict ----------------
__global__ void init_kernel(const float* __restrict__ dict, float* __restrict__ out) {
    size_t i = (size_t)blockIdx.x * blockDim.x + threadIdx.x;
    size_t stride = (size_t)gridDim.x * blockDim.x;
    const size_t nd2 = (size_t)VOCAB * DIM / 2;
    float2* od = (float2*)(out + OFF_DICT);
    const float2* dd = (const float2*)dict;
    for (size_t j = i; j < nd2; j += stride) {
        float2 d = dd[j];
        d.x *= MOM; d.y *= MOM;
        od[j] = d;
    }
    for (size_t j = i; j < M_ROWS; j += stride) { g_best[j] = 0ull; g_best2[j] = 0ull; }
    for (size_t j = i; j < VOCAB;  j += stride) g_cnt[j] = 0.0f;
    if (i == 0) { g_loss = 0.0; g_ncand = 0u; }
}

// ---------------- kernel C: pass-1 fp16-hi approx GEMM + candidate harvest ----------------
// 256 threads, 8 warps (2x4), warp tile 64x64, 4-stage cp.async pipeline.
__global__ void __launch_bounds__(256, 1)
gemm_approx() {
    extern __shared__ char sm[];
    uint32_t smb = smem_u32(sm);
    float* h_s = (float*)(sm + SM_H);
    unsigned long long* sbest = (unsigned long long*)(sm + SM_BEST);
    const int tid = threadIdx.x, lane = tid & 31, w = tid >> 5;
    const int wm = w >> 2, wn = w & 3;           // 2 x 4 warps, warp tile 64x64
    const int mt = blockIdx.x, nt = blockIdx.y;  // mt-major

    for (int i = tid; i < TN; i += 256) h_s[i] = g_h[nt * TN + i];
    if (tid < TM) sbest[tid] = 0ull;

    const uint32_t* gA = g_xh + (size_t)(mt * NCHUNK) * 2048;
    const uint32_t* gB = g_eh + (size_t)(nt * NCHUNK) * 4096;

    float acc[4][8][4];
    #pragma unroll
    for (int i = 0; i < 4; i++)
        #pragma unroll
        for (int j = 0; j < 8; j++)
            #pragma unroll
            for (int r = 0; r < 4; r++) acc[i][j][r] = 0.0f;

    auto issue = [&](int c) {
        uint32_t sb = smb + (uint32_t)(c & 3) * STAGE_BYTES;
        const uint32_t* a = gA + c * 2048;
        const uint32_t* b = gB + c * 4096;
        cp16(sb +         tid * 16, a + tid * 4);           // A 8KB
        cp16(sb +  4096 + tid * 16, a + 1024 + tid * 4);
        cp16(sb +  8192 + tid * 16, b + tid * 4);           // B 16KB
        cp16(sb + 12288 + tid * 16, b + 1024 + tid * 4);
        cp16(sb + 16384 + tid * 16, b + 2048 + tid * 4);
        cp16(sb + 20480 + tid * 16, b + 3072 + tid * 4);
        CP_COMMIT();
    };

    issue(0); issue(1); issue(2);

    for (int c = 0; c < NCHUNK; c++) {
        int rem = NCHUNK - 1 - c;            // groups newer than c
        if      (rem >= 2) CP_WAIT(2);
        else if (rem == 1) CP_WAIT(1);
        else               CP_WAIT(0);
        __syncthreads();                     // chunk c ready; reads of c-1 done
        if (c + 3 < NCHUNK) issue(c + 3);    // stage (c+3)&3 == (c-1)&3: safe

        int sbase = (c & 3) * STAGE_BYTES;
        #pragma unroll
        for (int ks = 0; ks < 2; ks++) {
            uint2 bf[8];
            #pragma unroll
            for (int j = 0; j < 8; j++)
                bf[j] = *(const uint2*)(sm + sbase + 8192 +
                                        (wn * 8 + j) * 512 + ks * 256 + lane * 8);
            uint4 af[4];
            #pragma unroll
            for (int i = 0; i < 4; i++)
                af[i] = *(const uint4*)(sm + sbase +
                                        (wm * 4 + i) * 1024 + ks * 512 + lane * 16);
            #pragma unroll
            for (int i = 0; i < 4; i++)
                #pragma unroll
                for (int j = 0; j < 8; j++)
                    MMA16(acc[i][j], af[i].x, af[i].y, af[i].z, af[i].w, bf[j].x, bf[j].y);
        }
    }
    __syncthreads();

    // ---- epilogue 1: tile-local per-row best ----
    #pragma unroll
    for (int i = 0; i < 4; i++) {
        #pragma unroll
        for (int half = 0; half < 2; half++) {
            int rowl = wm * 64 + i * 16 + (lane >> 2) + half * 8;
            float bs = -1e30f; int bc = 0;
            #pragma unroll
            for (int j = 0; j < 8; j++)
                #pragma unroll
                for (int p = 0; p < 2; p++) {
                    int coll = wn * 64 + j * 8 + (lane & 3) * 2 + p;
                    float s = acc[i][j][half * 2 + p] - h_s[coll];
                    int col = nt * TN + coll;
                    if (s > bs || (s == bs && col < bc)) { bs = s; bc = col; }
                }
            unsigned long long key =
                ((unsigned long long)fkey(bs) << 32) | (unsigned int)(VOCAB - 1 - bc);
            #pragma unroll
            for (int off = 1; off < 4; off <<= 1) {
                unsigned long long other = __shfl_xor_sync(0xffffffffu, key, off);
                if (other > key) key = other;
            }
            if ((lane & 3) == 0) atomicMax(&sbest[rowl], key);
        }
    }
    __syncthreads();

    // ---- epilogue 2: candidate harvest ----
    #pragma unroll
    for (int i = 0; i < 4; i++) {
        #pragma unroll
        for (int half = 0; half < 2; half++) {
            int rowl = wm * 64 + i * 16 + (lane >> 2) + half * 8;
            int rowg = mt * TM + rowl;
            float tb = keyscore(sbest[rowl]);
            float gb = keyscore(g_best[rowg]);          // racy lower bound: safe
            float thr = fmaxf(tb, gb) - MARGIN;
            #pragma unroll
            for (int j = 0; j < 8; j++)
                #pragma unroll
                for (int p = 0; p < 2; p++) {
                    int coll = wn * 64 + j * 8 + (lane & 3) * 2 + p;
                    float s = acc[i][j][half * 2 + p] - h_s[coll];
                    bool pred = (s >= thr);
                    unsigned int m = __ballot_sync(0xffffffffu, pred);
                    if (m) {
                        int leader = __ffs(m) - 1;
                        unsigned int base = 0;
                        if (lane == leader) base = atomicAdd(&g_ncand, (unsigned)__popc(m));
                        base = __shfl_sync(0xffffffffu, base, leader);
                        if (pred) {
                            unsigned int idx = base + __popc(m & ((1u << lane) - 1));
                            if (idx < CAP)
                                g_cand[idx] = (unsigned)rowg * 8192u + (unsigned)(nt * TN + coll);
                        }
                    }
                }
        }
    }
    __syncthreads();
    if (tid < TM) atomicMax(&g_best[(size_t)mt * TM + tid], sbest[tid]);
}

// ---------------- kernel C2: exact fp32 rescore of candidates ----------------
__global__ void rescore(const float* __restrict__ X) {
    int gw   = ((int)blockIdx.x * blockDim.x + threadIdx.x) >> 5;
    int nw   = (gridDim.x * blockDim.x) >> 5;
    int lane = threadIdx.x & 31;
    unsigned int n = g_ncand;
    if (n > CAP) n = CAP;
    for (unsigned int c = gw; c < n; c += nw) {
        uint32_t rc = g_cand[c];
        int row = rc >> 13, col = rc & 8191;
        const float4* xr = (const float4*)(X + (size_t)row * DIM);
        const float4* er = (const float4*)(g_e + (size_t)col * DIM);
        float s = 0.0f;
        #pragma unroll
        for (int t = lane; t < DIM / 4; t += 32) {
            float4 x = xr[t], e = er[t];
            s += x.x * e.x + x.y * e.y + x.z * e.z + x.w * e.w;
        }
        #pragma unroll
        for (int o = 16; o; o >>= 1) s += __shfl_xor_sync(0xffffffffu, s, o);
        if (lane == 0) {
            float sc = s - g_h[col];
            unsigned long long key =
                ((unsigned long long)fkey(sc) << 32) | (unsigned int)(VOCAB - 1 - col);
            atomicMax(&g_best2[row], key);
        }
    }
}

// ---------------- kernel D: gather x_q, loss, histogram, scatter x_sum ----------------
__global__ void scatter_kernel(const float* __restrict__ X, float* __restrict__ out) {
    int gw   = ((int)blockIdx.x * blockDim.x + threadIdx.x) >> 5;  // row
    int lane = threadIdx.x & 31;
    __shared__ double lred[8];
    double lsum = 0.0;
    if (gw < M_ROWS) {
        unsigned long long key = g_best2[gw];
        int k = VOCAB - 1 - (int)(key & 0xffffffffu);
        const float4* e4 = (const float4*)(g_e + (size_t)k * DIM);
        const float4* x4 = (const float4*)(X + (size_t)gw * DIM);
        float4*       q4 = (float4*)(out + (size_t)gw * DIM);
        float* nd = out + OFF_DICT + (size_t)k * DIM;
        float fs = 0.0f;
        #pragma unroll
        for (int c = lane; c < DIM / 4; c += 32) {
            float4 e = e4[c], x = x4[c];
            q4[c] = e;
            float dx = e.x - x.x, dy = e.y - x.y, dz = e.z - x.z, dw = e.w - x.w;
            fs += dx * dx + dy * dy + dz * dz + dw * dw;
            atomicAdd(nd + c * 4 + 0, x.x);
            atomicAdd(nd + c * 4 + 1, x.y);
            atomicAdd(nd + c * 4 + 2, x.z);
            atomicAdd(nd + c * 4 + 3, x.w);
        }
        #pragma unroll
        for (int o = 16; o; o >>= 1) fs += __shfl_xor_sync(0xffffffffu, fs, o);
        if (lane == 0) {
            atomicAdd(&g_cnt[k], 1.0f);
            lsum = (double)fs;
        }
    }
    int wid = threadIdx.x >> 5;
    if (lane == 0) lred[wid] = lsum;
    __syncthreads();
    if (threadIdx.x == 0) {
        double t = 0.0;
        for (int i = 0; i < 8; i++) t += lred[i];
        atomicAdd(&g_loss, t);
    }
}

// ---------------- kernel E: new_counts, loss, perplexity ----------------
__global__ void finalize_kernel(const float* __restrict__ counts, float* __restrict__ out) {
    __shared__ double red[32];
    __shared__ double s_total;
    int tid = threadIdx.x;
    double s = 0.0;
    for (int k = tid; k < VOCAB; k += 1024) {
        float nc = counts[k] * MOM + g_cnt[k];
        out[OFF_CNT + k] = nc;
        s += (double)nc;
    }
    #pragma unroll
    for (int o = 16; o; o >>= 1) s += __shfl_xor_sync(0xffffffffu, s, o);
    if ((tid & 31) == 0) red[tid >> 5] = s;
    __syncthreads();
    if (tid < 32) {
        double t = red[tid];
        #pragma unroll
        for (int o = 16; o; o >>= 1) t += __shfl_xor_sync(0xffffffffu, t, o);
        if (tid == 0) s_total = t;
    }
    __syncthreads();
    double total = s_total;
    double h = 0.0;
    for (int k = tid; k < VOCAB; k += 1024) {
        double p = (double)out[OFF_CNT + k] / total;
        h += p * log(p + 1e-10);
    }
    #pragma unroll
    for (int o = 16; o; o >>= 1) h += __shfl_xor_sync(0xffffffffu, h, o);
    if ((tid & 31) == 0) red[tid >> 5] = h;
    __syncthreads();
    if (tid == 0) {
        double t = 0.0;
        for (int i = 0; i < 32; i++) t += red[i];
        out[OFF_PERP] = (float)exp(-t);
        out[OFF_LOSS] = (float)(0.25 * g_loss / 16777216.0);
    }
}

// ---------------- launch ----------------
extern "C" void kernel_launch(void* const* d_in, const int* in_sizes, int n_in,
                              void* d_out, int out_size) {
    (void)in_sizes; (void)n_in; (void)out_size;
    const float* X      = (const float*)d_in[0];
    const float* dict   = (const float*)d_in[1];
    const float* counts = (const float*)d_in[2];
    float* out = (float*)d_out;

    cudaFuncSetAttribute(gemm_approx,
                         cudaFuncAttributeMaxDynamicSharedMemorySize, SM_TOTAL);

    compute_codewords<<<VOCAB, 128>>>(dict, counts);
    split_e<<<8192, 256>>>();
    split_x<<<32768, 256>>>(X);
    init_kernel<<<2048, 256>>>(dict, out);
    dim3 grid(M_ROWS / TM, VOCAB / TN);   // (256, 32), mt-major
    gemm_approx<<<grid, 256, SM_TOTAL>>>();
    rescore<<<2048, 256>>>(X);
    scatter_kernel<<<M_ROWS * 32 / 256, 256>>>(X, out);
    finalize_kernel<<<1, 1024>>>(counts, out);
}

// round 14
// speedup vs baseline: 1.5625x; 1.5625x over previous
#include <cuda_runtime.h>
#include <math.h>
#include <stdint.h>

// ---------------- problem constants ----------------
#define VOCAB   8192
#define DIM     512
#define M_ROWS  32768          // 8*4096
#define MOM     0.995f
// output packing (flat f32, tuple order): x_q | loss | perplexity | new_dict | new_counts
#define OFF_LOSS 16777216ull
#define OFF_PERP 16777217ull
#define OFF_DICT 16777218ull
#define OFF_CNT  20971522ull   // OFF_DICT + VOCAB*DIM

// ---------------- GEMM tiling (pass 1, int8 approx) ----------------
#define TM      128
#define TN      256
#define KC      32             // floats per K chunk = one m16n8k32 MMA
#define NCHUNK  (DIM / KC)     // 16
#define MARGIN  0.05f          // ~13 sigma of int8 quantization diff-error
#define CAP     16777216
// stage: A 4KB + B 8KB ; 4 stages
#define STAGE_BYTES 12288
#define SM_H     49152         // 4*12288
#define SM_SE    50176
#define SM_SX    51200
#define SM_BEST  51712
#define SM_TOTAL 52736

// ---------------- device scratch (static; no allocations) ----------------
__device__ float               g_e[VOCAB * DIM];
__device__ float               g_h[VOCAB];          // 0.5*||e||^2
__device__ float               g_sx[M_ROWS];        // per-row int8 scale (amax/127)
__device__ float               g_se[VOCAB];         // per-codeword int8 scale
__device__ unsigned long long  g_best[M_ROWS];      // approx packed keys
__device__ unsigned long long  g_best2[M_ROWS];     // exact packed keys
__device__ float               g_cnt[VOCAB];
__device__ double              g_loss;
__device__ unsigned int        g_ncand;
__device__ uint32_t            g_cand[CAP];
// fragment-packed int8 operands (4 int8 per u32 along k)
__device__ uint32_t            g_x8[M_ROWS * DIM / 4];   // 16MB
__device__ uint32_t            g_e8[VOCAB  * DIM / 4];   // 4MB

// ---------------- helpers ----------------
__device__ __forceinline__ uint32_t smem_u32(const void* p) {
    uint32_t a;
    asm("{ .reg .u64 t; cvta.to.shared.u64 t, %1; cvt.u32.u64 %0, t; }" : "=r"(a) : "l"(p));
    return a;
}
__device__ __forceinline__ void cp16(uint32_t dst, const void* src) {
    asm volatile("cp.async.ca.shared.global [%0], [%1], 16;" :: "r"(dst), "l"(src));
}
#define CP_COMMIT() asm volatile("cp.async.commit_group;")
#define CP_WAIT(n)  asm volatile("cp.async.wait_group %0;" :: "n"(n))

#define MMAI8(d, a0, a1, a2, a3, b0, b1)                                      \
    asm volatile(                                                             \
        "mma.sync.aligned.m16n8k32.row.col.s32.s8.s8.s32 "                    \
        "{%0,%1,%2,%3}, {%4,%5,%6,%7}, {%8,%9}, {%0,%1,%2,%3};"               \
        : "+r"(d[0]), "+r"(d[1]), "+r"(d[2]), "+r"(d[3])                      \
        : "r"(a0), "r"(a1), "r"(a2), "r"(a3), "r"(b0), "r"(b1))

__device__ __forceinline__ unsigned int fkey(float s) {
    unsigned int ub = __float_as_uint(s);
    return (ub & 0x80000000u) ? ~ub : (ub | 0x80000000u);
}
__device__ __forceinline__ float keyscore(unsigned long long k) {
    unsigned int ub = (unsigned int)(k >> 32);
    unsigned int orig = (ub & 0x80000000u) ? (ub & 0x7fffffffu) : ~ub;
    return __uint_as_float(orig);   // k==0 -> -NaN; callers use fmaxf
}
__device__ __forceinline__ uint32_t q4pack(float4 v, float inv) {
    int a = __float2int_rn(v.x * inv), b = __float2int_rn(v.y * inv);
    int c = __float2int_rn(v.z * inv), d = __float2int_rn(v.w * inv);
    return (a & 0xff) | ((b & 0xff) << 8) | ((c & 0xff) << 16) | ((d & 0xff) << 24);
}

// ---------------- kernel A: codewords + half norms + per-codeword amax ----------------
__global__ void compute_codewords(const float* __restrict__ dict,
                                  const float* __restrict__ counts) {
    int k = blockIdx.x;
    int t = threadIdx.x;
    float inv = 1.0f / counts[k];
    const float4* src = (const float4*)(dict + (size_t)k * DIM);
    float4*       dst = (float4*)(g_e + (size_t)k * DIM);
    float4 v = src[t];
    v.x *= inv; v.y *= inv; v.z *= inv; v.w *= inv;
    dst[t] = v;
    float s = v.x * v.x + v.y * v.y + v.z * v.z + v.w * v.w;
    float a = fmaxf(fmaxf(fabsf(v.x), fabsf(v.y)), fmaxf(fabsf(v.z), fabsf(v.w)));
    #pragma unroll
    for (int o = 16; o; o >>= 1) {
        s += __shfl_xor_sync(0xffffffffu, s, o);
        a = fmaxf(a, __shfl_xor_sync(0xffffffffu, a, o));
    }
    __shared__ float ws[4], wa[4];
    if ((t & 31) == 0) { ws[t >> 5] = s; wa[t >> 5] = a; }
    __syncthreads();
    if (t == 0) {
        g_h[k] = 0.5f * (ws[0] + ws[1] + ws[2] + ws[3]);
        float am = fmaxf(fmaxf(wa[0], wa[1]), fmaxf(wa[2], wa[3]));
        g_se[k] = fmaxf(am, 1e-20f) * (1.0f / 127.0f);
    }
}

// ---------------- per-row amax of X ----------------
__global__ void amax_x(const float* __restrict__ X) {
    int row  = ((int)blockIdx.x * blockDim.x + threadIdx.x) >> 5;
    int lane = threadIdx.x & 31;
    const float4* xr = (const float4*)(X + (size_t)row * DIM);
    float m = 0.0f;
    #pragma unroll
    for (int t = lane; t < DIM / 4; t += 32) {
        float4 v = xr[t];
        m = fmaxf(m, fmaxf(fmaxf(fabsf(v.x), fabsf(v.y)), fmaxf(fabsf(v.z), fabsf(v.w))));
    }
    #pragma unroll
    for (int o = 16; o; o >>= 1) m = fmaxf(m, __shfl_xor_sync(0xffffffffu, m, o));
    if (lane == 0) g_sx[row] = fmaxf(m, 1e-20f) * (1.0f / 127.0f);
}

// ---------------- pack X / E into fragment-ordered int8 ----------------
// A u32 index: [mt(256)][c(16)][msub(8)][lane(32)][reg(4)]
// reg bits: bit0 -> row+8 ; bit1 -> k+16. u32 = 4 int8 along k.
__global__ void pack_x(const float* __restrict__ X) {
    int o = blockIdx.x * 256 + threadIdx.x;       // 4194304 total
    int reg  =  o        & 3;
    int lane = (o >> 2)  & 31;
    int msub = (o >> 7)  & 7;
    int c    = (o >> 10) & 15;
    int mt   =  o >> 14;
    int m = mt * 128 + msub * 16 + (lane >> 2) + (reg & 1) * 8;
    int k = c * 32 + (lane & 3) * 4 + (reg >> 1) * 16;
    float inv = 1.0f / g_sx[m];
    float4 v = *(const float4*)(X + (size_t)m * DIM + k);
    g_x8[o] = q4pack(v, inv);
}

// B u32 index: [nt(32)][c(16)][nsub(32)][lane(32)][reg(2)]
__global__ void pack_e() {
    int o = blockIdx.x * 256 + threadIdx.x;       // 1048576 total
    int reg  =  o        & 1;
    int lane = (o >> 1)  & 31;
    int nsub = (o >> 6)  & 31;
    int c    = (o >> 11) & 15;
    int nt   =  o >> 15;
    int n = nt * 256 + nsub * 8 + (lane >> 2);
    int k = c * 32 + (lane & 3) * 4 + reg * 16;
    float inv = 1.0f / g_se[n];
    float4 v = *(const float4*)(g_e + (size_t)n * DIM + k);
    g_e8[o] = q4pack(v, inv);
}

// ---------------- kernel B: init scratch + new_dict = 0.995*dict ----------------
__global__ void init_kernel(const float* __restrict__ dict, float* __restrict__ out) {
    size_t i = (size_t)blockIdx.x * blockDim.x + threadIdx.x;
    size_t stride = (size_t)gridDim.x * blockDim.x;
    const size_t nd2 = (size_t)VOCAB * DIM / 2;
    float2* od = (float2*)(out + OFF_DICT);
    const float2* dd = (const float2*)dict;
    for (size_t j = i; j < nd2; j += stride) {
        float2 d = dd[j];
        d.x *= MOM; d.y *= MOM;
        od[j] = d;
    }
    for (size_t j = i; j < M_ROWS; j += stride) { g_best[j] = 0ull; g_best2[j] = 0ull; }
    for (size_t j = i; j < VOCAB;  j += stride) g_cnt[j] = 0.0f;
    if (i == 0) { g_loss = 0.0; g_ncand = 0u; }
}

// ---------------- kernel C: pass-1 int8 approx GEMM + candidate harvest ----------------
// 512 threads, 16 warps (2x8), warp tile 64x32, 4-stage cp.async pipeline.
__global__ void __launch_bounds__(512, 1)
gemm_approx() {
    extern __shared__ char sm[];
    uint32_t smb = smem_u32(sm);
    float* h_s  = (float*)(sm + SM_H);
    float* se_s = (float*)(sm + SM_SE);
    float* sx_s = (float*)(sm + SM_SX);
    unsigned long long* sbest = (unsigned long long*)(sm + SM_BEST);
    const int tid = threadIdx.x, lane = tid & 31, w = tid >> 5;
    const int wm = w >> 3, wn = w & 7;           // 2 x 8 warps, warp tile 64x32
    const int mt = blockIdx.x, nt = blockIdx.y;  // mt-major

    for (int i = tid; i < TN; i += 512) {
        h_s[i]  = g_h[nt * TN + i];
        se_s[i] = g_se[nt * TN + i];
    }
    if (tid < TM) { sx_s[tid] = g_sx[mt * TM + tid]; sbest[tid] = 0ull; }

    const uint32_t* gA = g_x8 + (size_t)(mt * NCHUNK) * 1024;
    const uint32_t* gB = g_e8 + (size_t)(nt * NCHUNK) * 2048;

    int acc[4][4][4];
    #pragma unroll
    for (int i = 0; i < 4; i++)
        #pragma unroll
        for (int j = 0; j < 4; j++)
            #pragma unroll
            for (int r = 0; r < 4; r++) acc[i][j][r] = 0;

    auto issue = [&](int c) {
        uint32_t sb = smb + (uint32_t)(c & 3) * STAGE_BYTES;
        if (tid < 256) cp16(sb + tid * 16, gA + c * 1024 + tid * 4);   // A 4KB
        cp16(sb + 4096 + tid * 16, gB + c * 2048 + tid * 4);           // B 8KB
        CP_COMMIT();
    };

    issue(0); issue(1); issue(2);

    for (int c = 0; c < NCHUNK; c++) {
        int rem = NCHUNK - 1 - c;
        if      (rem >= 2) CP_WAIT(2);
        else if (rem == 1) CP_WAIT(1);
        else               CP_WAIT(0);
        __syncthreads();                     // chunk c ready; reads of c-1 done
        if (c + 3 < NCHUNK) issue(c + 3);    // stage (c+3)&3 == (c-1)&3: safe

        int sbase = (c & 3) * STAGE_BYTES;
        uint2 bf[4];
        #pragma unroll
        for (int j = 0; j < 4; j++)
            bf[j] = *(const uint2*)(sm + sbase + 4096 + (wn * 4 + j) * 256 + lane * 8);
        uint4 af[4];
        #pragma unroll
        for (int i = 0; i < 4; i++)
            af[i] = *(const uint4*)(sm + sbase + (wm * 4 + i) * 512 + lane * 16);
        #pragma unroll
        for (int i = 0; i < 4; i++)
            #pragma unroll
            for (int j = 0; j < 4; j++)
                MMAI8(acc[i][j], af[i].x, af[i].y, af[i].z, af[i].w, bf[j].x, bf[j].y);
    }
    __syncthreads();

    // ---- epilogue 1: tile-local per-row best ----
    #pragma unroll
    for (int i = 0; i < 4; i++) {
        #pragma unroll
        for (int half = 0; half < 2; half++) {
            int rowl = wm * 64 + i * 16 + (lane >> 2) + half * 8;
            float sx = sx_s[rowl];
            float bs = -1e30f; int bc = 0;
            #pragma unroll
            for (int j = 0; j < 4; j++)
                #pragma unroll
                for (int p = 0; p < 2; p++) {
                    int coll = wn * 32 + j * 8 + (lane & 3) * 2 + p;
                    float s = sx * se_s[coll] * (float)acc[i][j][half * 2 + p] - h_s[coll];
                    int col = nt * TN + coll;
                    if (s > bs || (s == bs && col < bc)) { bs = s; bc = col; }
                }
            unsigned long long key =
                ((unsigned long long)fkey(bs) << 32) | (unsigned int)(VOCAB - 1 - bc);
            #pragma unroll
            for (int off = 1; off < 4; off <<= 1) {
                unsigned long long other = __shfl_xor_sync(0xffffffffu, key, off);
                if (other > key) key = other;
            }
            if ((lane & 3) == 0) atomicMax(&sbest[rowl], key);
        }
    }
    __syncthreads();

    // ---- epilogue 2: candidate harvest (margin below max(tile best, global approx)) ----
    #pragma unroll
    for (int i = 0; i < 4; i++) {
        #pragma unroll
        for (int half = 0; half < 2; half++) {
            int rowl = wm * 64 + i * 16 + (lane >> 2) + half * 8;
            int rowg = mt * TM + rowl;
            float sx = sx_s[rowl];
            float tb = keyscore(sbest[rowl]);
            float gb = keyscore(g_best[rowg]);          // racy lower bound: safe
            float thr = fmaxf(tb, gb) - MARGIN;
            #pragma unroll
            for (int j = 0; j < 4; j++)
                #pragma unroll
                for (int p = 0; p < 2; p++) {
                    int coll = wn * 32 + j * 8 + (lane & 3) * 2 + p;
                    float s = sx * se_s[coll] * (float)acc[i][j][half * 2 + p] - h_s[coll];
                    bool pred = (s >= thr);
                    unsigned int m = __ballot_sync(0xffffffffu, pred);
                    if (m) {
                        int leader = __ffs(m) - 1;
                        unsigned int base = 0;
                        if (lane == leader) base = atomicAdd(&g_ncand, (unsigned)__popc(m));
                        base = __shfl_sync(0xffffffffu, base, leader);
                        if (pred) {
                            unsigned int idx = base + __popc(m & ((1u << lane) - 1));
                            if (idx < CAP)
                                g_cand[idx] = (unsigned)rowg * 8192u + (unsigned)(nt * TN + coll);
                        }
                    }
                }
        }
    }
    __syncthreads();
    if (tid < TM) atomicMax(&g_best[(size_t)mt * TM + tid], sbest[tid]);
}

// ---------------- kernel C2: exact fp32 rescore of candidates ----------------
__global__ void rescore(const float* __restrict__ X) {
    int gw   = ((int)blockIdx.x * blockDim.x + threadIdx.x) >> 5;
    int nw   = (gridDim.x * blockDim.x) >> 5;
    int lane = threadIdx.x & 31;
    unsigned int n = g_ncand;
    if (n > CAP) n = CAP;
    for (unsigned int c = gw; c < n; c += nw) {
        uint32_t rc = g_cand[c];
        int row = rc >> 13, col = rc & 8191;
        const float4* xr = (const float4*)(X + (size_t)row * DIM);
        const float4* er = (const float4*)(g_e + (size_t)col * DIM);
        float s = 0.0f;
        #pragma unroll
        for (int t = lane; t < DIM / 4; t += 32) {
            float4 x = xr[t], e = er[t];
            s += x.x * e.x + x.y * e.y + x.z * e.z + x.w * e.w;
        }
        #pragma unroll
        for (int o = 16; o; o >>= 1) s += __shfl_xor_sync(0xffffffffu, s, o);
        if (lane == 0) {
            float sc = s - g_h[col];
            unsigned long long key =
                ((unsigned long long)fkey(sc) << 32) | (unsigned int)(VOCAB - 1 - col);
            atomicMax(&g_best2[row], key);
        }
    }
}

// ---------------- kernel D: gather x_q, loss, histogram, scatter x_sum ----------------
__global__ void scatter_kernel(const float* __restrict__ X, float* __restrict__ out) {
    int gw   = ((int)blockIdx.x * blockDim.x + threadIdx.x) >> 5;  // row
    int lane = threadIdx.x & 31;
    __shared__ double lred[8];
    double lsum = 0.0;
    if (gw < M_ROWS) {
        unsigned long long key = g_best2[gw];
        int k = VOCAB - 1 - (int)(key & 0xffffffffu);
        const float4* e4 = (const float4*)(g_e + (size_t)k * DIM);
        const float4* x4 = (const float4*)(X + (size_t)gw * DIM);
        float4*       q4 = (float4*)(out + (size_t)gw * DIM);
        float* nd = out + OFF_DICT + (size_t)k * DIM;
        float fs = 0.0f;
        #pragma unroll
        for (int c = lane; c < DIM / 4; c += 32) {
            float4 e = e4[c], x = x4[c];
            q4[c] = e;
            float dx = e.x - x.x, dy = e.y - x.y, dz = e.z - x.z, dw = e.w - x.w;
            fs += dx * dx + dy * dy + dz * dz + dw * dw;
            atomicAdd(nd + c * 4 + 0, x.x);
            atomicAdd(nd + c * 4 + 1, x.y);
            atomicAdd(nd + c * 4 + 2, x.z);
            atomicAdd(nd + c * 4 + 3, x.w);
        }
        #pragma unroll
        for (int o = 16; o; o >>= 1) fs += __shfl_xor_sync(0xffffffffu, fs, o);
        if (lane == 0) {
            atomicAdd(&g_cnt[k], 1.0f);
            lsum = (double)fs;
        }
    }
    int wid = threadIdx.x >> 5;
    if (lane == 0) lred[wid] = lsum;
    __syncthreads();
    if (threadIdx.x == 0) {
        double t = 0.0;
        for (int i = 0; i < 8; i++) t += lred[i];
        atomicAdd(&g_loss, t);
    }
}

// ---------------- kernel E: new_counts, loss, perplexity ----------------
__global__ void finalize_kernel(const float* __restrict__ counts, float* __restrict__ out) {
    __shared__ double red[32];
    __shared__ double s_total;
    int tid = threadIdx.x;
    double s = 0.0;
    for (int k = tid; k < VOCAB; k += 1024) {
        float nc = counts[k] * MOM + g_cnt[k];
        out[OFF_CNT + k] = nc;
        s += (double)nc;
    }
    #pragma unroll
    for (int o = 16; o; o >>= 1) s += __shfl_xor_sync(0xffffffffu, s, o);
    if ((tid & 31) == 0) red[tid >> 5] = s;
    __syncthreads();
    if (tid < 32) {
        double t = red[tid];
        #pragma unroll
        for (int o = 16; o; o >>= 1) t += __shfl_xor_sync(0xffffffffu, t, o);
        if (tid == 0) s_total = t;
    }
    __syncthreads();
    double total = s_total;
    double h = 0.0;
    for (int k = tid; k < VOCAB; k += 1024) {
        double p = (double)out[OFF_CNT + k] / total;
        h += p * log(p + 1e-10);
    }
    #pragma unroll
    for (int o = 16; o; o >>= 1) h += __shfl_xor_sync(0xffffffffu, h, o);
    if ((tid & 31) == 0) red[tid >> 5] = h;
    __syncthreads();
    if (tid == 0) {
        double t = 0.0;
        for (int i = 0; i < 32; i++) t += red[i];
        out[OFF_PERP] = (float)exp(-t);
        out[OFF_LOSS] = (float)(0.25 * g_loss / 16777216.0);
    }
}

// ---------------- launch ----------------
extern "C" void kernel_launch(void* const* d_in, const int* in_sizes, int n_in,
                              void* d_out, int out_size) {
    (void)in_sizes; (void)n_in; (void)out_size;
    const float* X      = (const float*)d_in[0];
    const float* dict   = (const float*)d_in[1];
    const float* counts = (const float*)d_in[2];
    float* out = (float*)d_out;

    cudaFuncSetAttribute(gemm_approx,
                         cudaFuncAttributeMaxDynamicSharedMemorySize, SM_TOTAL);

    compute_codewords<<<VOCAB, 128>>>(dict, counts);
    amax_x<<<4096, 256>>>(X);
    pack_e<<<4096, 256>>>();
    pack_x<<<16384, 256>>>(X);
    init_kernel<<<2048, 256>>>(dict, out);
    dim3 grid(M_ROWS / TM, VOCAB / TN);   // (256, 32), mt-major
    gemm_approx<<<grid, 512, SM_TOTAL>>>();
    rescore<<<2048, 256>>>(X);
    scatter_kernel<<<M_ROWS * 32 / 256, 256>>>(X, out);
    finalize_kernel<<<1, 1024>>>(counts, out);
}

// round 16
// speedup vs baseline: 1.6079x; 1.0290x over previous
#include <cuda_runtime.h>
#include <math.h>
#include <stdint.h>

// ---------------- problem constants ----------------
#define VOCAB   8192
#define DIM     512
#define M_ROWS  32768          // 8*4096
#define MOM     0.995f
// output packing (flat f32, tuple order): x_q | loss | perplexity | new_dict | new_counts
#define OFF_LOSS 16777216ull
#define OFF_PERP 16777217ull
#define OFF_DICT 16777218ull
#define OFF_CNT  20971522ull   // OFF_DICT + VOCAB*DIM

// ---------------- GEMM tiling (pass 1, int8 approx) ----------------
#define TM      128
#define TN      256
#define KC      64             // floats per K chunk = two m16n8k32 MMA k-steps
#define NCHUNK  (DIM / KC)     // 8
#define MARGIN  0.05f          // ~13 sigma of int8 quantization diff-error
#define CAP     16777216
// stage: A 8KB + B 16KB ; 4 stages
#define STAGE_BYTES 24576
#define SM_H     98304         // 4*24576
#define SM_SE    99328
#define SM_SX    100352
#define SM_BEST  100864
#define SM_TOTAL 101888

// ---------------- device scratch (static; no allocations) ----------------
__device__ float               g_e[VOCAB * DIM];
__device__ float               g_h[VOCAB];          // 0.5*||e||^2
__device__ float               g_sx[M_ROWS];        // per-row int8 scale (amax/127)
__device__ float               g_se[VOCAB];         // per-codeword int8 scale
__device__ unsigned long long  g_best[M_ROWS];      // approx packed keys
__device__ unsigned long long  g_best2[M_ROWS];     // exact packed keys
__device__ float               g_cnt[VOCAB];
__device__ double              g_loss;
__device__ unsigned int        g_ncand;
__device__ uint32_t            g_cand[CAP];
// fragment-packed int8 operands (4 int8 per u32 along k); layout unchanged from R14
__device__ uint32_t            g_x8[M_ROWS * DIM / 4];   // 16MB
__device__ uint32_t            g_e8[VOCAB  * DIM / 4];   // 4MB

// ---------------- helpers ----------------
__device__ __forceinline__ uint32_t smem_u32(const void* p) {
    uint32_t a;
    asm("{ .reg .u64 t; cvta.to.shared.u64 t, %1; cvt.u32.u64 %0, t; }" : "=r"(a) : "l"(p));
    return a;
}
__device__ __forceinline__ void cp16(uint32_t dst, const void* src) {
    asm volatile("cp.async.ca.shared.global [%0], [%1], 16;" :: "r"(dst), "l"(src));
}
#define CP_COMMIT() asm volatile("cp.async.commit_group;")
#define CP_WAIT(n)  asm volatile("cp.async.wait_group %0;" :: "n"(n))

#define MMAI8(d, a0, a1, a2, a3, b0, b1)                                      \
    asm volatile(                                                             \
        "mma.sync.aligned.m16n8k32.row.col.s32.s8.s8.s32 "                    \
        "{%0,%1,%2,%3}, {%4,%5,%6,%7}, {%8,%9}, {%0,%1,%2,%3};"               \
        : "+r"(d[0]), "+r"(d[1]), "+r"(d[2]), "+r"(d[3])                      \
        : "r"(a0), "r"(a1), "r"(a2), "r"(a3), "r"(b0), "r"(b1))

__device__ __forceinline__ unsigned int fkey(float s) {
    unsigned int ub = __float_as_uint(s);
    return (ub & 0x80000000u) ? ~ub : (ub | 0x80000000u);
}
__device__ __forceinline__ float keyscore(unsigned long long k) {
    unsigned int ub = (unsigned int)(k >> 32);
    unsigned int orig = (ub & 0x80000000u) ? (ub & 0x7fffffffu) : ~ub;
    return __uint_as_float(orig);   // k==0 -> -NaN; callers use fmaxf
}
__device__ __forceinline__ uint32_t q4pack(float4 v, float inv) {
    int a = __float2int_rn(v.x * inv), b = __float2int_rn(v.y * inv);
    int c = __float2int_rn(v.z * inv), d = __float2int_rn(v.w * inv);
    return (a & 0xff) | ((b & 0xff) << 8) | ((c & 0xff) << 16) | ((d & 0xff) << 24);
}

// ---------------- kernel A: codewords + half norms + per-codeword amax ----------------
__global__ void compute_codewords(const float* __restrict__ dict,
                                  const float* __restrict__ counts) {
    int k = blockIdx.x;
    int t = threadIdx.x;
    float inv = 1.0f / counts[k];
    const float4* src = (const float4*)(dict + (size_t)k * DIM);
    float4*       dst = (float4*)(g_e + (size_t)k * DIM);
    float4 v = src[t];
    v.x *= inv; v.y *= inv; v.z *= inv; v.w *= inv;
    dst[t] = v;
    float s = v.x * v.x + v.y * v.y + v.z * v.z + v.w * v.w;
    float a = fmaxf(fmaxf(fabsf(v.x), fabsf(v.y)), fmaxf(fabsf(v.z), fabsf(v.w)));
    #pragma unroll
    for (int o = 16; o; o >>= 1) {
        s += __shfl_xor_sync(0xffffffffu, s, o);
        a = fmaxf(a, __shfl_xor_sync(0xffffffffu, a, o));
    }
    __shared__ float ws[4], wa[4];
    if ((t & 31) == 0) { ws[t >> 5] = s; wa[t >> 5] = a; }
    __syncthreads();
    if (t == 0) {
        g_h[k] = 0.5f * (ws[0] + ws[1] + ws[2] + ws[3]);
        float am = fmaxf(fmaxf(wa[0], wa[1]), fmaxf(wa[2], wa[3]));
        g_se[k] = fmaxf(am, 1e-20f) * (1.0f / 127.0f);
    }
}

// ---------------- per-row amax of X ----------------
__global__ void amax_x(const float* __restrict__ X) {
    int row  = ((int)blockIdx.x * blockDim.x + threadIdx.x) >> 5;
    int lane = threadIdx.x & 31;
    const float4* xr = (const float4*)(X + (size_t)row * DIM);
    float m = 0.0f;
    #pragma unroll
    for (int t = lane; t < DIM / 4; t += 32) {
        float4 v = xr[t];
        m = fmaxf(m, fmaxf(fmaxf(fabsf(v.x), fabsf(v.y)), fmaxf(fabsf(v.z), fabsf(v.w))));
    }
    #pragma unroll
    for (int o = 16; o; o >>= 1) m = fmaxf(m, __shfl_xor_sync(0xffffffffu, m, o));
    if (lane == 0) g_sx[row] = fmaxf(m, 1e-20f) * (1.0f / 127.0f);
}

// ---------------- pack X / E into fragment-ordered int8 (layout as R14) ----------------
// A u32 index: [mt(256)][c32(16)][msub(8)][lane(32)][reg(4)]
__global__ void pack_x(const float* __restrict__ X) {
    int o = blockIdx.x * 256 + threadIdx.x;       // 4194304 total
    int reg  =  o        & 3;
    int lane = (o >> 2)  & 31;
    int msub = (o >> 7)  & 7;
    int c    = (o >> 10) & 15;
    int mt   =  o >> 14;
    int m = mt * 128 + msub * 16 + (lane >> 2) + (reg & 1) * 8;
    int k = c * 32 + (lane & 3) * 4 + (reg >> 1) * 16;
    float inv = 1.0f / g_sx[m];
    float4 v = *(const float4*)(X + (size_t)m * DIM + k);
    g_x8[o] = q4pack(v, inv);
}

// B u32 index: [nt(32)][c32(16)][nsub(32)][lane(32)][reg(2)]
__global__ void pack_e() {
    int o = blockIdx.x * 256 + threadIdx.x;       // 1048576 total
    int reg  =  o        & 1;
    int lane = (o >> 1)  & 31;
    int nsub = (o >> 6)  & 31;
    int c    = (o >> 11) & 15;
    int nt   =  o >> 15;
    int n = nt * 256 + nsub * 8 + (lane >> 2);
    int k = c * 32 + (lane & 3) * 4 + reg * 16;
    float inv = 1.0f / g_se[n];
    float4 v = *(const float4*)(g_e + (size_t)n * DIM + k);
    g_e8[o] = q4pack(v, inv);
}

// ---------------- kernel B: init scratch + new_dict = 0.995*dict ----------------
__global__ void init_kernel(const float* __restrict__ dict, float* __restrict__ out) {
    size_t i = (size_t)blockIdx.x * blockDim.x + threadIdx.x;
    size_t stride = (size_t)gridDim.x * blockDim.x;
    const size_t nd2 = (size_t)VOCAB * DIM / 2;
    float2* od = (float2*)(out + OFF_DICT);
    const float2* dd = (const float2*)dict;
    for (size_t j = i; j < nd2; j += stride) {
        float2 d = dd[j];
        d.x *= MOM; d.y *= MOM;
        od[j] = d;
    }
    for (size_t j = i; j < M_ROWS; j += stride) { g_best[j] = 0ull; g_best2[j] = 0ull; }
    for (size_t j = i; j < VOCAB;  j += stride) g_cnt[j] = 0.0f;
    if (i == 0) { g_loss = 0.0; g_ncand = 0u; }
}

// ---------------- kernel C: pass-1 int8 approx GEMM + candidate harvest ----------------
// 512 threads, 16 warps (2x8), warp tile 64x32, KC=64 (2 k-steps/chunk), 4-stage pipeline.
__global__ void __launch_bounds__(512, 1)
gemm_approx() {
    extern __shared__ char sm[];
    uint32_t smb = smem_u32(sm);
    float* h_s  = (float*)(sm + SM_H);
    float* se_s = (float*)(sm + SM_SE);
    float* sx_s = (float*)(sm + SM_SX);
    unsigned long long* sbest = (unsigned long long*)(sm + SM_BEST);
    const int tid = threadIdx.x, lane = tid & 31, w = tid >> 5;
    const int wm = w >> 3, wn = w & 7;           // 2 x 8 warps, warp tile 64x32
    const int mt = blockIdx.x, nt = blockIdx.y;  // mt-major

    for (int i = tid; i < TN; i += 512) {
        h_s[i]  = g_h[nt * TN + i];
        se_s[i] = g_se[nt * TN + i];
    }
    if (tid < TM) { sx_s[tid] = g_sx[mt * TM + tid]; sbest[tid] = 0ull; }

    // chunk of 64 floats = 2 consecutive 1024-u32 (A) / 2048-u32 (B) packed blocks
    const uint32_t* gA = g_x8 + (size_t)(mt * 16) * 1024;
    const uint32_t* gB = g_e8 + (size_t)(nt * 16) * 2048;

    int acc[4][4][4];
    #pragma unroll
    for (int i = 0; i < 4; i++)
        #pragma unroll
        for (int j = 0; j < 4; j++)
            #pragma unroll
            for (int r = 0; r < 4; r++) acc[i][j][r] = 0;

    auto issue = [&](int c) {
        uint32_t sb = smb + (uint32_t)(c & 3) * STAGE_BYTES;
        const uint32_t* a = gA + (size_t)c * 2048;
        const uint32_t* b = gB + (size_t)c * 4096;
        cp16(sb +         tid * 16, a + tid * 4);          // A: 8KB (ks0|ks1)
        cp16(sb +  8192 + tid * 16, b + tid * 4);          // B ks0 first 8KB
        cp16(sb + 16384 + tid * 16, b + 2048 + tid * 4);   // B ks1 second 8KB
        CP_COMMIT();
    };

    issue(0); issue(1); issue(2);

    for (int c = 0; c < NCHUNK; c++) {
        int rem = NCHUNK - 1 - c;
        if      (rem >= 2) CP_WAIT(2);
        else if (rem == 1) CP_WAIT(1);
        else               CP_WAIT(0);
        __syncthreads();                     // chunk c ready; reads of c-1 done
        if (c + 3 < NCHUNK) issue(c + 3);    // stage (c+3)&3 == (c-1)&3: safe

        int sbase = (c & 3) * STAGE_BYTES;
        #pragma unroll
        for (int ks = 0; ks < 2; ks++) {
            int ab = sbase + ks * 4096;
            int bb = sbase + 8192 + ks * 8192;
            uint2 bf[4];
            #pragma unroll
            for (int j = 0; j < 4; j++)
                bf[j] = *(const uint2*)(sm + bb + (wn * 4 + j) * 256 + lane * 8);
            uint4 af[4];
            #pragma unroll
            for (int i = 0; i < 4; i++)
                af[i] = *(const uint4*)(sm + ab + (wm * 4 + i) * 512 + lane * 16);
            #pragma unroll
            for (int i = 0; i < 4; i++)
                #pragma unroll
                for (int j = 0; j < 4; j++)
                    MMAI8(acc[i][j], af[i].x, af[i].y, af[i].z, af[i].w, bf[j].x, bf[j].y);
        }
    }
    __syncthreads();

    // ---- epilogue 1: tile-local per-row best ----
    #pragma unroll
    for (int i = 0; i < 4; i++) {
        #pragma unroll
        for (int half = 0; half < 2; half++) {
            int rowl = wm * 64 + i * 16 + (lane >> 2) + half * 8;
            float sx = sx_s[rowl];
            float bs = -1e30f; int bc = 0;
            #pragma unroll
            for (int j = 0; j < 4; j++)
                #pragma unroll
                for (int p = 0; p < 2; p++) {
                    int coll = wn * 32 + j * 8 + (lane & 3) * 2 + p;
                    float s = sx * se_s[coll] * (float)acc[i][j][half * 2 + p] - h_s[coll];
                    int col = nt * TN + coll;
                    if (s > bs || (s == bs && col < bc)) { bs = s; bc = col; }
                }
            unsigned long long key =
                ((unsigned long long)fkey(bs) << 32) | (unsigned int)(VOCAB - 1 - bc);
            #pragma unroll
            for (int off = 1; off < 4; off <<= 1) {
                unsigned long long other = __shfl_xor_sync(0xffffffffu, key, off);
                if (other > key) key = other;
            }
            if ((lane & 3) == 0) atomicMax(&sbest[rowl], key);
        }
    }
    __syncthreads();

    // ---- epilogue 2: candidate harvest (margin below max(tile best, global approx)) ----
    #pragma unroll
    for (int i = 0; i < 4; i++) {
        #pragma unroll
        for (int half = 0; half < 2; half++) {
            int rowl = wm * 64 + i * 16 + (lane >> 2) + half * 8;
            int rowg = mt * TM + rowl;
            float sx = sx_s[rowl];
            float tb = keyscore(sbest[rowl]);
            float gb = keyscore(g_best[rowg]);          // racy lower bound: safe
            float thr = fmaxf(tb, gb) - MARGIN;
            #pragma unroll
            for (int j = 0; j < 4; j++)
                #pragma unroll
                for (int p = 0; p < 2; p++) {
                    int coll = wn * 32 + j * 8 + (lane & 3) * 2 + p;
                    float s = sx * se_s[coll] * (float)acc[i][j][half * 2 + p] - h_s[coll];
                    bool pred = (s >= thr);
                    unsigned int m = __ballot_sync(0xffffffffu, pred);
                    if (m) {
                        int leader = __ffs(m) - 1;
                        unsigned int base = 0;
                        if (lane == leader) base = atomicAdd(&g_ncand, (unsigned)__popc(m));
                        base = __shfl_sync(0xffffffffu, base, leader);
                        if (pred) {
                            unsigned int idx = base + __popc(m & ((1u << lane) - 1));
                            if (idx < CAP)
                                g_cand[idx] = (unsigned)rowg * 8192u + (unsigned)(nt * TN + coll);
                        }
                    }
                }
        }
    }
    __syncthreads();
    if (tid < TM) atomicMax(&g_best[(size_t)mt * TM + tid], sbest[tid]);
}

// ---------------- kernel C2: exact fp32 rescore of candidates ----------------
__global__ void rescore(const float* __restrict__ X) {
    int gw   = ((int)blockIdx.x * blockDim.x + threadIdx.x) >> 5;
    int nw   = (gridDim.x * blockDim.x) >> 5;
    int lane = threadIdx.x & 31;
    unsigned int n = g_ncand;
    if (n > CAP) n = CAP;
    for (unsigned int c = gw; c < n; c += nw) {
        uint32_t rc = g_cand[c];
        int row = rc >> 13, col = rc & 8191;
        const float4* xr = (const float4*)(X + (size_t)row * DIM);
        const float4* er = (const float4*)(g_e + (size_t)col * DIM);
        float s = 0.0f;
        #pragma unroll
        for (int t = lane; t < DIM / 4; t += 32) {
            float4 x = xr[t], e = er[t];
            s += x.x * e.x + x.y * e.y + x.z * e.z + x.w * e.w;
        }
        #pragma unroll
        for (int o = 16; o; o >>= 1) s += __shfl_xor_sync(0xffffffffu, s, o);
        if (lane == 0) {
            float sc = s - g_h[col];
            unsigned long long key =
                ((unsigned long long)fkey(sc) << 32) | (unsigned int)(VOCAB - 1 - col);
            atomicMax(&g_best2[row], key);
        }
    }
}

// ---------------- kernel D: gather x_q, loss, histogram, scatter x_sum ----------------
__global__ void scatter_kernel(const float* __restrict__ X, float* __restrict__ out) {
    int gw   = ((int)blockIdx.x * blockDim.x + threadIdx.x) >> 5;  // row
    int lane = threadIdx.x & 31;
    __shared__ double lred[8];
    double lsum = 0.0;
    if (gw < M_ROWS) {
        unsigned long long key = g_best2[gw];
        int k = VOCAB - 1 - (int)(key & 0xffffffffu);
        const float4* e4 = (const float4*)(g_e + (size_t)k * DIM);
        const float4* x4 = (const float4*)(X + (size_t)gw * DIM);
        float4*       q4 = (float4*)(out + (size_t)gw * DIM);
        float* nd = out + OFF_DICT + (size_t)k * DIM;
        float fs = 0.0f;
        #pragma unroll
        for (int c = lane; c < DIM / 4; c += 32) {
            float4 e = e4[c], x = x4[c];
            q4[c] = e;
            float dx = e.x - x.x, dy = e.y - x.y, dz = e.z - x.z, dw = e.w - x.w;
            fs += dx * dx + dy * dy + dz * dz + dw * dw;
            atomicAdd(nd + c * 4 + 0, x.x);
            atomicAdd(nd + c * 4 + 1, x.y);
            atomicAdd(nd + c * 4 + 2, x.z);
            atomicAdd(nd + c * 4 + 3, x.w);
        }
        #pragma unroll
        for (int o = 16; o; o >>= 1) fs += __shfl_xor_sync(0xffffffffu, fs, o);
        if (lane == 0) {
            atomicAdd(&g_cnt[k], 1.0f);
            lsum = (double)fs;
        }
    }
    int wid = threadIdx.x >> 5;
    if (lane == 0) lred[wid] = lsum;
    __syncthreads();
    if (threadIdx.x == 0) {
        double t = 0.0;
        for (int i = 0; i < 8; i++) t += lred[i];
        atomicAdd(&g_loss, t);
    }
}

// ---------------- kernel E: new_counts, loss, perplexity ----------------
__global__ void finalize_kernel(const float* __restrict__ counts, float* __restrict__ out) {
    __shared__ double red[32];
    __shared__ double s_total;
    int tid = threadIdx.x;
    double s = 0.0;
    for (int k = tid; k < VOCAB; k += 1024) {
        float nc = counts[k] * MOM + g_cnt[k];
        out[OFF_CNT + k] = nc;
        s += (double)nc;
    }
    #pragma unroll
    for (int o = 16; o; o >>= 1) s += __shfl_xor_sync(0xffffffffu, s, o);
    if ((tid & 31) == 0) red[tid >> 5] = s;
    __syncthreads();
    if (tid < 32) {
        double t = red[tid];
        #pragma unroll
        for (int o = 16; o; o >>= 1) t += __shfl_xor_sync(0xffffffffu, t, o);
        if (tid == 0) s_total = t;
    }
    __syncthreads();
    double total = s_total;
    double h = 0.0;
    for (int k = tid; k < VOCAB; k += 1024) {
        double p = (double)out[OFF_CNT + k] / total;
        h += p * log(p + 1e-10);
    }
    #pragma unroll
    for (int o = 16; o; o >>= 1) h += __shfl_xor_sync(0xffffffffu, h, o);
    if ((tid & 31) == 0) red[tid >> 5] = h;
    __syncthreads();
    if (tid == 0) {
        double t = 0.0;
        for (int i = 0; i < 32; i++) t += red[i];
        out[OFF_PERP] = (float)exp(-t);
        out[OFF_LOSS] = (float)(0.25 * g_loss / 16777216.0);
    }
}

// ---------------- launch ----------------
extern "C" void kernel_launch(void* const* d_in, const int* in_sizes, int n_in,
                              void* d_out, int out_size) {
    (void)in_sizes; (void)n_in; (void)out_size;
    const float* X      = (const float*)d_in[0];
    const float* dict   = (const float*)d_in[1];
    const float* counts = (const float*)d_in[2];
    float* out = (float*)d_out;

    cudaFuncSetAttribute(gemm_approx,
                         cudaFuncAttributeMaxDynamicSharedMemorySize, SM_TOTAL);

    compute_codewords<<<VOCAB, 128>>>(dict, counts);
    amax_x<<<4096, 256>>>(X);
    pack_e<<<4096, 256>>>();
    pack_x<<<16384, 256>>>(X);
    init_kernel<<<2048, 256>>>(dict, out);
    dim3 grid(M_ROWS / TM, VOCAB / TN);   // (256, 32), mt-major
    gemm_approx<<<grid, 512, SM_TOTAL>>>();
    rescore<<<2048, 256>>>(X);
    scatter_kernel<<<M_ROWS * 32 / 256, 256>>>(X, out);
    finalize_kernel<<<1, 1024>>>(counts, out);
}